// round 17
// baseline (speedup 1.0000x reference)
#include <cuda_runtime.h>
#include <cuda_fp16.h>
#include <cstdint>

namespace {
constexpr int Bn = 4, Hn = 16, S = 2048, Dh = 64;
constexpr int BH = Bn * Hn;
constexpr int MQA = 256;          // pass A q rows per unit (M=32 per warp)
constexpr int MQB = 256;          // pass B q rows per unit (M=32 per warp)
constexpr int NKA = 128;          // pass A keys per tile
constexpr int NTA = S / NKA;      // 16
constexpr int NK = 64;            // pass B keys per tile
constexpr int NT = S / NK;        // 32
constexpr int THREADS = 256;
constexpr int NELEM = BH * S * Dh;
constexpr float LOG2E = 1.4426950408889634f;
constexpr int NUNITS_A = BH * (S / MQA);  // 512
constexpr int NUNITS_B = BH * (S / MQB);  // 512
constexpr int GRID = 296;                 // 2 CTAs/SM x 148 SMs (persistent)
constexpr int QK_BLOCKS = NELEM / 4 / THREADS;            // 8192
constexpr int VT_BLOCKS = (S / 32) * (Dh / 32) * BH;      // 8192

// smem: Q persistent [0,32K); ring region [32K, 80K); mask [80K, 88K)
// pass A: K 16KB x3 at OFF_RING + buf*16384
// pass B: K 8KB x3 at OFF_RING + buf*8192 ; V 8KB x3 at OFF_VB + buf*8192
constexpr int OFF_RING = 32768;
constexpr int OFF_VB   = 32768 + 24576;   // 57344
constexpr int OFF_MS   = 81920;           // 2048 f32 (log-domain mask)
constexpr unsigned SMEM_BYTES = OFF_MS + S * 4;   // 90,112 B -> 2 CTAs/SM
}

__device__ __half g_Qhi[NELEM];
__device__ __half g_Khi[NELEM];
__device__ __half g_VThi[NELEM];   // [bh][d][s]

__device__ unsigned g_ctr;
__device__ unsigned g_flag[NUNITS_A];
__device__ float    g_linv_f[BH * S];   // per q-row -log2(rowsum)

__device__ __forceinline__ uint32_t s2u(const void* p) {
    uint32_t a;
    asm("{ .reg .u64 t; cvta.to.shared.u64 t, %1; cvt.u32.u64 %0, t; }" : "=r"(a) : "l"(p));
    return a;
}
__device__ __forceinline__ uint32_t swz(uint32_t o) { return o ^ ((o >> 3) & 0x70); }

#define LDSM4(r, a) \
    asm volatile("ldmatrix.sync.aligned.m8n8.x4.shared.b16 {%0,%1,%2,%3},[%4];" \
                 : "=r"((r)[0]), "=r"((r)[1]), "=r"((r)[2]), "=r"((r)[3]) : "r"(a))
#define CP16(dst, src) \
    asm volatile("cp.async.ca.shared.global [%0], [%1], 16;" :: "r"(dst), "l"(src))
#define CP_COMMIT() asm volatile("cp.async.commit_group;" ::: "memory")
#define CP_WAIT0()  asm volatile("cp.async.wait_group 0;" ::: "memory")
#define CP_WAIT1()  asm volatile("cp.async.wait_group 1;" ::: "memory")

__device__ __forceinline__ void mma_f16(float c[4], const uint32_t a[4],
                                        uint32_t b0, uint32_t b1) {
    asm volatile(
        "mma.sync.aligned.m16n8k16.row.col.f32.f16.f16.f32 "
        "{%0,%1,%2,%3},{%4,%5,%6,%7},{%8,%9},{%0,%1,%2,%3};"
        : "+f"(c[0]), "+f"(c[1]), "+f"(c[2]), "+f"(c[3])
        : "r"(a[0]), "r"(a[1]), "r"(a[2]), "r"(a[3]), "r"(b0), "r"(b1));
}

__device__ __forceinline__ float ex2f(float x) {
    float r;
    asm("ex2.approx.ftz.f32 %0, %1;" : "=f"(r) : "f"(x));
    return r;
}
// pack two f32 into f16x2: lo half = x, hi half = y
__device__ __forceinline__ uint32_t packh2(float x, float y) {
    uint32_t r;
    asm("cvt.rn.f16x2.f32 %0, %1, %2;" : "=r"(r) : "f"(y), "f"(x));
    return r;
}

// ---------------- fused pre-kernel: QK convert + V transpose ----------------
__global__ void conv_all(const float* __restrict__ q, const float* __restrict__ k,
                         const float* __restrict__ v) {
    __shared__ float t[32][33];
    const int bid = blockIdx.x;
    if (bid < QK_BLOCKS) {
        if (bid == 0) {
            if (threadIdx.x == 0) g_ctr = 0u;
            for (int i = threadIdx.x; i < NUNITS_A; i += blockDim.x) g_flag[i] = 0u;
        }
        size_t i4 = (size_t)bid * blockDim.x + threadIdx.x;
        size_t e = i4 * 4;
        float4 qv = *reinterpret_cast<const float4*>(q + e);
        float4 kv = *reinterpret_cast<const float4*>(k + e);
        qv.x *= 0.125f; qv.y *= 0.125f; qv.z *= 0.125f; qv.w *= 0.125f;
        uint2 wq;
        wq.x = packh2(qv.x, qv.y);
        wq.y = packh2(qv.z, qv.w);
        *reinterpret_cast<uint2*>(g_Qhi + e) = wq;
        uint2 wk;
        wk.x = packh2(kv.x, kv.y);
        wk.y = packh2(kv.z, kv.w);
        *reinterpret_cast<uint2*>(g_Khi + e) = wk;
    } else {
        const int vb = bid - QK_BLOCKS;
        const int bh = vb >> 7;
        const int rem = vb & 127;
        const int s0 = (rem >> 1) << 5;
        const int d0 = (rem & 1) << 5;
        const int tx = threadIdx.x & 31, ty = threadIdx.x >> 5;
        #pragma unroll
        for (int j = 0; j < 4; ++j)
            t[ty + 8 * j][tx] = v[((size_t)bh * S + s0 + ty + 8 * j) * Dh + d0 + tx];
        __syncthreads();
        #pragma unroll
        for (int j = 0; j < 4; ++j) {
            float x = t[tx][ty + 8 * j];
            size_t o = ((size_t)bh * Dh + d0 + ty + 8 * j) * S + s0 + tx;
            g_VThi[o] = __float2half_rn(x);
        }
    }
}

// ---------------- persistent main kernel ----------------
__global__ __launch_bounds__(THREADS, 2)
void attn_persist(const int* __restrict__ mask, float* __restrict__ out,
                  float* __restrict__ p_attn)
{
    extern __shared__ char sm[];
    __shared__ unsigned s_uid;
    const uint32_t sb = s2u(sm);
    const int tid = threadIdx.x;
    const int w = tid >> 5, lane = tid & 31;
    float* msf = reinterpret_cast<float*>(sm + OFF_MS);

    for (;;) {
        __syncthreads();   // previous unit fully done with smem + s_uid
        if (tid == 0) s_uid = atomicAdd(&g_ctr, 1u);
        __syncthreads();
        const unsigned uid = s_uid;
        if (uid >= (unsigned)(NUNITS_A + NUNITS_B)) break;
        const bool isA = uid < (unsigned)NUNITS_A;
        const int u  = isA ? (int)uid : (int)(uid - NUNITS_A);
        const int qt = u & 7, bh = u >> 3;
        const int b  = bh >> 4;
        const int q0 = qt * 256;

        for (int i = tid; i < S; i += THREADS)
            msf[i] = (mask[b * S + i] != 0) ? 0.0f : -1e30f;

        // ---- stage Q (256 rows, 32KB at base 0; disjoint from ring) ----
        #pragma unroll
        for (int i = 0; i < 8; ++i) {
            int fi = tid + i * THREADS;
            int row = fi >> 3, c8 = fi & 7;
            CP16(sb + swz((uint32_t)(row * 128 + c8 * 16)),
                 g_Qhi + ((size_t)bh * S + q0 + row) * Dh + c8 * 8);
        }
        CP_COMMIT(); CP_WAIT0(); __syncthreads();
        uint32_t qa[2][4][4];   // 2 m-tiles: rows w*32 + mt*16 + ...
        #pragma unroll
        for (int mt = 0; mt < 2; ++mt)
            #pragma unroll
            for (int ks = 0; ks < 4; ++ks) {
                uint32_t a = sb +
                    swz((uint32_t)((w * 32 + mt * 16 + (lane & 15)) * 128 + ks * 32 +
                                   ((lane >> 4) & 1) * 16));
                LDSM4(qa[mt][ks], a);
            }

        if (isA) {
            // ======== PASS A UNIT: rowsums, M=32 per warp ========
            float rs[4] = {0.f, 0.f, 0.f, 0.f};
            #pragma unroll
            for (int i = 0; i < 4; ++i) {   // preload K tile 0 into ring buf0
                int fi = tid + i * THREADS;
                int row = fi >> 3, c8 = fi & 7;
                CP16(sb + OFF_RING + swz((uint32_t)(row * 128 + c8 * 16)),
                     g_Khi + ((size_t)bh * S + row) * Dh + c8 * 8);
            }
            CP_COMMIT();
            for (int t = 0; t < NTA; ++t) {
                const int t0 = t * NKA;
                if (t + 1 < NTA) {
                    const uint32_t dstb = sb + OFF_RING + ((t + 1) % 3) * 16384;
                    #pragma unroll
                    for (int i = 0; i < 4; ++i) {
                        int fi = tid + i * THREADS;
                        int row = fi >> 3, c8 = fi & 7;
                        CP16(dstb + swz((uint32_t)(row * 128 + c8 * 16)),
                             g_Khi + ((size_t)bh * S + t0 + NKA + row) * Dh + c8 * 8);
                    }
                    CP_COMMIT(); CP_WAIT1();
                } else {
                    CP_WAIT0();
                }
                __syncthreads();           // ring-3: single sync per tile
                const uint32_t kbase = sb + OFF_RING + (t % 3) * 16384;
                #pragma unroll
                for (int g = 0; g < 8; ++g) {
                    float c[4][4];
                    #pragma unroll
                    for (int f = 0; f < 4; ++f)
                        #pragma unroll
                        for (int e = 0; e < 4; ++e) c[f][e] = 0.f;
                    uint32_t rowb = g * 16 + (lane & 15);
                    #pragma unroll
                    for (int ks = 0; ks < 4; ++ks) {
                        uint32_t kh[4];
                        LDSM4(kh, kbase + swz(rowb * 128 + ks * 32 + ((lane >> 4) & 1) * 16));
                        mma_f16(c[0], qa[0][ks], kh[0], kh[2]);
                        mma_f16(c[1], qa[0][ks], kh[1], kh[3]);
                        mma_f16(c[2], qa[1][ks], kh[0], kh[2]);
                        mma_f16(c[3], qa[1][ks], kh[1], kh[3]);
                    }
                    int colA = t0 + g * 16 + 2 * (lane & 3);
                    float2 mA = *reinterpret_cast<const float2*>(msf + colA);
                    float2 mB = *reinterpret_cast<const float2*>(msf + colA + 8);
                    rs[0] += ex2f(fmaf(c[0][0], LOG2E, mA.x)) + ex2f(fmaf(c[0][1], LOG2E, mA.y));
                    rs[1] += ex2f(fmaf(c[0][2], LOG2E, mA.x)) + ex2f(fmaf(c[0][3], LOG2E, mA.y));
                    rs[0] += ex2f(fmaf(c[1][0], LOG2E, mB.x)) + ex2f(fmaf(c[1][1], LOG2E, mB.y));
                    rs[1] += ex2f(fmaf(c[1][2], LOG2E, mB.x)) + ex2f(fmaf(c[1][3], LOG2E, mB.y));
                    rs[2] += ex2f(fmaf(c[2][0], LOG2E, mA.x)) + ex2f(fmaf(c[2][1], LOG2E, mA.y));
                    rs[3] += ex2f(fmaf(c[2][2], LOG2E, mA.x)) + ex2f(fmaf(c[2][3], LOG2E, mA.y));
                    rs[2] += ex2f(fmaf(c[3][0], LOG2E, mB.x)) + ex2f(fmaf(c[3][1], LOG2E, mB.y));
                    rs[3] += ex2f(fmaf(c[3][2], LOG2E, mB.x)) + ex2f(fmaf(c[3][3], LOG2E, mB.y));
                }
            }
            #pragma unroll
            for (int r = 0; r < 4; ++r) {
                rs[r] += __shfl_xor_sync(0xffffffffu, rs[r], 1);
                rs[r] += __shfl_xor_sync(0xffffffffu, rs[r], 2);
            }
            if ((lane & 3) == 0) {
                int rbase = bh * S + q0 + w * 32;
                g_linv_f[rbase + (lane >> 2)]      = -__log2f(rs[0]);
                g_linv_f[rbase + 8 + (lane >> 2)]  = -__log2f(rs[1]);
                g_linv_f[rbase + 16 + (lane >> 2)] = -__log2f(rs[2]);
                g_linv_f[rbase + 24 + (lane >> 2)] = -__log2f(rs[3]);
            }
            __syncthreads();
            __threadfence();                       // release: linv visible before flag
            if (tid == 0) atomicExch(&g_flag[u], 1u);
        } else {
            // ======== PASS B UNIT: p_attn + out, M=32 per warp ========
            if (tid == 0) {
                while (atomicAdd(&g_flag[u], 0u) == 0u) __nanosleep(200);
                __threadfence();
            }
            __syncthreads();
            const int r0g = q0 + w * 32 + (lane >> 2);
            float linv[4];
            #pragma unroll
            for (int j = 0; j < 4; ++j)
                linv[j] = __ldcg(&g_linv_f[bh * S + r0g + j * 8]);

            float oacc0[8][4], oacc1[8][4];
            #pragma unroll
            for (int d = 0; d < 8; ++d)
                #pragma unroll
                for (int e = 0; e < 4; ++e) { oacc0[d][e] = 0.f; oacc1[d][e] = 0.f; }

            float* pa_row[4];
            #pragma unroll
            for (int j = 0; j < 4; ++j)
                pa_row[j] = p_attn + ((size_t)bh * S + r0g + j * 8) * S;

            auto loadB = [&](int t, int buf) {
                const int t0 = t * NK;
                const uint32_t kbuf = sb + OFF_RING + buf * 8192;
                const uint32_t vbuf = sb + OFF_VB + buf * 8192;
                #pragma unroll
                for (int i = 0; i < 2; ++i) {
                    int fi = tid + i * THREADS;
                    int row = fi >> 3, c8 = fi & 7;
                    uint32_t soff = swz((uint32_t)(row * 128 + c8 * 16));
                    CP16(kbuf + soff,
                         g_Khi + ((size_t)bh * S + t0 + row) * Dh + c8 * 8);
                    CP16(vbuf + soff,
                         g_VThi + ((size_t)bh * Dh + row) * S + t0 + c8 * 8);
                }
            };

            loadB(0, 0); CP_COMMIT();
            for (int t = 0; t < NT; ++t) {
                const int t0 = t * NK;
                if (t + 1 < NT) { loadB(t + 1, (t + 1) % 3); CP_COMMIT(); CP_WAIT1(); }
                else            { CP_WAIT0(); }
                __syncthreads();           // ring-3: single sync per tile
                const uint32_t kb = sb + OFF_RING + (t % 3) * 8192;
                const uint32_t vb = sb + OFF_VB + (t % 3) * 8192;

                #pragma unroll
                for (int g = 0; g < 4; ++g) {
                    float c[4][4];
                    #pragma unroll
                    for (int f = 0; f < 4; ++f)
                        #pragma unroll
                        for (int e = 0; e < 4; ++e) c[f][e] = 0.f;
                    uint32_t rowb = g * 16 + (lane & 15);
                    #pragma unroll
                    for (int ks = 0; ks < 4; ++ks) {
                        uint32_t kh[4];
                        LDSM4(kh, kb + swz(rowb * 128 + ks * 32 + ((lane >> 4) & 1) * 16));
                        mma_f16(c[0], qa[0][ks], kh[0], kh[2]);
                        mma_f16(c[1], qa[0][ks], kh[1], kh[3]);
                        mma_f16(c[2], qa[1][ks], kh[0], kh[2]);
                        mma_f16(c[3], qa[1][ks], kh[1], kh[3]);
                    }
                    int colA = t0 + g * 16 + 2 * (lane & 3);
                    float2 mA = *reinterpret_cast<const float2*>(msf + colA);
                    float2 mB = *reinterpret_cast<const float2*>(msf + colA + 8);
                    uint32_t pa[4], pb[4];
                    // mt0 (fragments 0,1 ; linv[0], linv[1])
                    {
                        float p00 = ex2f(fmaf(c[0][0], LOG2E, linv[0]) + mA.x);
                        float p01 = ex2f(fmaf(c[0][1], LOG2E, linv[0]) + mA.y);
                        float p10 = ex2f(fmaf(c[0][2], LOG2E, linv[1]) + mA.x);
                        float p11 = ex2f(fmaf(c[0][3], LOG2E, linv[1]) + mA.y);
                        float q00 = ex2f(fmaf(c[1][0], LOG2E, linv[0]) + mB.x);
                        float q01 = ex2f(fmaf(c[1][1], LOG2E, linv[0]) + mB.y);
                        float q10 = ex2f(fmaf(c[1][2], LOG2E, linv[1]) + mB.x);
                        float q11 = ex2f(fmaf(c[1][3], LOG2E, linv[1]) + mB.y);
                        *reinterpret_cast<float2*>(pa_row[0] + colA)     = make_float2(p00, p01);
                        *reinterpret_cast<float2*>(pa_row[0] + colA + 8) = make_float2(q00, q01);
                        *reinterpret_cast<float2*>(pa_row[1] + colA)     = make_float2(p10, p11);
                        *reinterpret_cast<float2*>(pa_row[1] + colA + 8) = make_float2(q10, q11);
                        pa[0] = packh2(p00, p01);
                        pa[1] = packh2(p10, p11);
                        pa[2] = packh2(q00, q01);
                        pa[3] = packh2(q10, q11);
                    }
                    // mt1 (fragments 2,3 ; linv[2], linv[3])
                    {
                        float p00 = ex2f(fmaf(c[2][0], LOG2E, linv[2]) + mA.x);
                        float p01 = ex2f(fmaf(c[2][1], LOG2E, linv[2]) + mA.y);
                        float p10 = ex2f(fmaf(c[2][2], LOG2E, linv[3]) + mA.x);
                        float p11 = ex2f(fmaf(c[2][3], LOG2E, linv[3]) + mA.y);
                        float q00 = ex2f(fmaf(c[3][0], LOG2E, linv[2]) + mB.x);
                        float q01 = ex2f(fmaf(c[3][1], LOG2E, linv[2]) + mB.y);
                        float q10 = ex2f(fmaf(c[3][2], LOG2E, linv[3]) + mB.x);
                        float q11 = ex2f(fmaf(c[3][3], LOG2E, linv[3]) + mB.y);
                        *reinterpret_cast<float2*>(pa_row[2] + colA)     = make_float2(p00, p01);
                        *reinterpret_cast<float2*>(pa_row[2] + colA + 8) = make_float2(q00, q01);
                        *reinterpret_cast<float2*>(pa_row[3] + colA)     = make_float2(p10, p11);
                        *reinterpret_cast<float2*>(pa_row[3] + colA + 8) = make_float2(q10, q11);
                        pb[0] = packh2(p00, p01);
                        pb[1] = packh2(p10, p11);
                        pb[2] = packh2(q00, q01);
                        pb[3] = packh2(q10, q11);
                    }
                    // PV: shared V fragments feed both m-tiles
                    uint32_t kcb = g * 32 + ((lane >> 4) & 1) * 16;
                    #pragma unroll
                    for (int db2 = 0; db2 < 4; ++db2) {
                        uint32_t vh[4];
                        LDSM4(vh, vb + swz((uint32_t)((db2 * 16 + (lane & 15)) * 128) + kcb));
                        mma_f16(oacc0[db2 * 2],     pa, vh[0], vh[2]);
                        mma_f16(oacc0[db2 * 2 + 1], pa, vh[1], vh[3]);
                        mma_f16(oacc1[db2 * 2],     pb, vh[0], vh[2]);
                        mma_f16(oacc1[db2 * 2 + 1], pb, vh[1], vh[3]);
                    }
                }
            }
            #pragma unroll
            for (int db = 0; db < 8; ++db) {
                int col = db * 8 + 2 * (lane & 3);
                *reinterpret_cast<float2*>(out + ((size_t)bh * S + r0g) * Dh + col) =
                    make_float2(oacc0[db][0], oacc0[db][1]);
                *reinterpret_cast<float2*>(out + ((size_t)bh * S + r0g + 8) * Dh + col) =
                    make_float2(oacc0[db][2], oacc0[db][3]);
                *reinterpret_cast<float2*>(out + ((size_t)bh * S + r0g + 16) * Dh + col) =
                    make_float2(oacc1[db][0], oacc1[db][1]);
                *reinterpret_cast<float2*>(out + ((size_t)bh * S + r0g + 24) * Dh + col) =
                    make_float2(oacc1[db][2], oacc1[db][3]);
            }
        }
    }
}

extern "C" void kernel_launch(void* const* d_in, const int* in_sizes, int n_in,
                              void* d_out, int out_size) {
    const float* q = (const float*)d_in[0];
    const float* k = (const float*)d_in[1];
    const float* v = (const float*)d_in[2];
    const int* mask = (const int*)d_in[3];

    float* out = (float*)d_out;
    float* p_attn = out + (size_t)Bn * Hn * S * Dh;

    conv_all<<<QK_BLOCKS + VT_BLOCKS, THREADS>>>(q, k, v);

    cudaFuncSetAttribute(attn_persist, cudaFuncAttributeMaxDynamicSharedMemorySize, SMEM_BYTES);
    attn_persist<<<GRID, THREADS, SMEM_BYTES>>>(mask, out, p_attn);
}